// round 3
// baseline (speedup 1.0000x reference)
#include <cuda_runtime.h>
#include <cuda_bf16.h>

// Problem constants (fixed by the dataset)
#define MAXN 100000
#define MAXE 3200000
#define INC1 64
#define HIDC 128
#define OUTC2 64

// ---------------- device scratch (no allocations allowed) ----------------
__device__ float g_buf_o1[MAXN * HIDC];  // relu(layer1 output)            [N,128]
__device__ float g_buf_xs[MAXN * INC1];  // dinv*x, later reused for g2     [N,64]
__device__ float g_buf_a [MAXN * INC1];  // aggregated xs                   [N,64]
__device__ int   g_rowptr[MAXN + 1];
__device__ int   g_cursor[MAXN];
__device__ int   g_col[MAXE];            // CSR col (src ids), grouped by dst
__device__ float g_dinv[MAXN];
__device__ int   g_cnt[MAXN];

// ---------------- CSR build ----------------
__global__ void zero_cnt_kernel(int n) {
    int i = blockIdx.x * blockDim.x + threadIdx.x;
    if (i < n) g_cnt[i] = 0;
}

__global__ void count_kernel(const int* __restrict__ dst, int E) {
    int e = blockIdx.x * blockDim.x + threadIdx.x;
    if (e < E) atomicAdd(&g_cnt[dst[e]], 1);
}

// One-block scan over n counts -> exclusive row_ptr, cursor copy, dinv.
// Degree = cnt + 1 (self loop), always > 0.
__global__ void scan_kernel(int n) {
    __shared__ int sums[1024];
    int t = threadIdx.x;
    int chunk = (n + 1023) >> 10;
    int beg = t * chunk;
    int end = beg + chunk; if (end > n) end = n;
    int s = 0;
    if (beg < n) for (int i = beg; i < end; i++) s += g_cnt[i];
    sums[t] = s;
    __syncthreads();
    for (int off = 1; off < 1024; off <<= 1) {
        int v = sums[t];
        int add = (t >= off) ? sums[t - off] : 0;
        __syncthreads();
        sums[t] = v + add;
        __syncthreads();
    }
    int run = (t == 0) ? 0 : sums[t - 1];
    if (beg < n) {
        for (int i = beg; i < end; i++) {
            g_rowptr[i] = run;
            g_cursor[i] = run;
            g_dinv[i]   = rsqrtf((float)(g_cnt[i] + 1));
            run += g_cnt[i];
        }
    }
    if (t == 1023) g_rowptr[n] = sums[1023];
}

__global__ void fill_kernel(const int* __restrict__ src,
                            const int* __restrict__ dst, int E) {
    int e = blockIdx.x * blockDim.x + threadIdx.x;
    if (e < E) {
        int d = dst[e];
        int pos = atomicAdd(&g_cursor[d], 1);
        g_col[pos] = src[e];
    }
}

// ---------------- xs = dinv .* x (prescale, [N,64]) ----------------
__global__ void scale_x_kernel(const float* __restrict__ X, float* __restrict__ XS, int n) {
    int i = blockIdx.x * blockDim.x + threadIdx.x;      // one float2 per thread
    if (i >= n * 32) return;
    int row = i >> 5;
    float di = g_dinv[row];
    float2 v = ((const float2*)X)[i];
    v.x *= di; v.y *= di;
    ((float2*)XS)[i] = v;
}

// ---------------- Aggregation (CSR gather), one warp per node, 64 ch ----------------
// acc init = G[d] (self-loop term). Optional epilogue: dinv*acc + b (EPI=1), else raw sum.
template <int EPI>
__global__ void __launch_bounds__(256)
agg64_kernel(const float* __restrict__ G, const float* __restrict__ b,
             float* __restrict__ O, int n) {
    int warp = (blockIdx.x * blockDim.x + threadIdx.x) >> 5;
    int lane = threadIdx.x & 31;
    if (warp >= n) return;
    const int d = warp;
    const float2* __restrict__ Gv = (const float2*)G;
    float2 acc = Gv[d * 32 + lane];              // self loop
    int e = g_rowptr[d];
    const int end = g_rowptr[d + 1];
    for (; e + 8 <= end; e += 8) {
        int s0 = g_col[e + 0], s1 = g_col[e + 1], s2 = g_col[e + 2], s3 = g_col[e + 3];
        int s4 = g_col[e + 4], s5 = g_col[e + 5], s6 = g_col[e + 6], s7 = g_col[e + 7];
        float2 a0 = Gv[s0 * 32 + lane];
        float2 a1 = Gv[s1 * 32 + lane];
        float2 a2 = Gv[s2 * 32 + lane];
        float2 a3 = Gv[s3 * 32 + lane];
        float2 a4 = Gv[s4 * 32 + lane];
        float2 a5 = Gv[s5 * 32 + lane];
        float2 a6 = Gv[s6 * 32 + lane];
        float2 a7 = Gv[s7 * 32 + lane];
        acc.x += a0.x; acc.y += a0.y;
        acc.x += a1.x; acc.y += a1.y;
        acc.x += a2.x; acc.y += a2.y;
        acc.x += a3.x; acc.y += a3.y;
        acc.x += a4.x; acc.y += a4.y;
        acc.x += a5.x; acc.y += a5.y;
        acc.x += a6.x; acc.y += a6.y;
        acc.x += a7.x; acc.y += a7.y;
    }
    for (; e < end; e++) {
        int s = g_col[e];
        float2 a = Gv[s * 32 + lane];
        acc.x += a.x; acc.y += a.y;
    }
    if (EPI) {
        const float di = g_dinv[d];
        float2 bi = ((const float2*)b)[lane];
        acc.x = di * acc.x + bi.x;
        acc.y = di * acc.y + bi.y;
    }
    ((float2*)O)[d * 32 + lane] = acc;
}

// ---------------- GEMM: G[i,:] = epi( X[i,:] @ W ) ----------------
// EPI=1: relu(dinv*acc + b) ; EPI=0: dinv*acc
template <int INC, int OUTC, int RY, int RPB, int EPI>
__global__ void __launch_bounds__(OUTC * RY)
gemm_kernel(const float* __restrict__ X, const float* __restrict__ W,
            const float* __restrict__ b, float* __restrict__ G, int n) {
    __shared__ float Ws[INC * OUTC];
    __shared__ float Xs[RY][INC];
    const int tx = threadIdx.x;        // output channel
    const int ty = threadIdx.y;        // row slot
    const int tid = ty * OUTC + tx;
    const int nthr = OUTC * RY;
    for (int i = tid; i < INC * OUTC; i += nthr) Ws[i] = W[i];
    __syncthreads();
    const int base = blockIdx.x * RPB;
    for (int r0 = 0; r0 < RPB; r0 += RY) {
        for (int i = tid; i < RY * INC; i += nthr) {
            int rr = base + r0 + i / INC;
            Xs[i / INC][i % INC] = (rr < n) ? X[rr * INC + (i % INC)] : 0.f;
        }
        __syncthreads();
        int row = base + r0 + ty;
        if (row < n) {
            float acc = 0.f;
#pragma unroll
            for (int k = 0; k < INC; k++)
                acc += Xs[ty][k] * Ws[k * OUTC + tx];
            float di = g_dinv[row];
            if (EPI) {
                G[row * OUTC + tx] = fmaxf(di * acc + b[tx], 0.f);
            } else {
                G[row * OUTC + tx] = di * acc;
            }
        }
        __syncthreads();
    }
}

// ---------------- launch ----------------
extern "C" void kernel_launch(void* const* d_in, const int* in_sizes, int n_in,
                              void* d_out, int out_size) {
    const float* x  = (const float*)d_in[0];
    const int*   ei = (const int*)d_in[1];     // int32 (JAX x64-disabled truncates int64)
    const float* W1 = (const float*)d_in[2];
    const float* b1 = (const float*)d_in[3];
    const float* W2 = (const float*)d_in[4];
    const float* b2 = (const float*)d_in[5];
    float* out = (float*)d_out;

    const int n = in_sizes[0] / INC1;     // 100000
    const int E = in_sizes[1] / 2;        // 3200000
    const int* src = ei;
    const int* dst = ei + E;

    float* d_o1 = nullptr; cudaGetSymbolAddress((void**)&d_o1, g_buf_o1);
    float* d_xs = nullptr; cudaGetSymbolAddress((void**)&d_xs, g_buf_xs);
    float* d_a  = nullptr; cudaGetSymbolAddress((void**)&d_a,  g_buf_a);

    // 1) CSR build (shared by both layers)
    zero_cnt_kernel<<<(n + 255) / 256, 256>>>(n);
    count_kernel<<<(E + 255) / 256, 256>>>(dst, E);
    scan_kernel<<<1, 1024>>>(n);
    fill_kernel<<<(E + 255) / 256, 256>>>(src, dst, E);

    // 2) xs = dinv .* x   (64 ch)
    scale_x_kernel<<<(n * 32 + 255) / 256, 256>>>(x, d_xs, n);
    // 3) a[d] = xs[d] + sum_{s in N(d)} xs[s]    (64-ch gather)
    agg64_kernel<0><<<(n * 32 + 255) / 256, 256>>>(d_xs, nullptr, d_a, n);
    // 4) o1 = relu(dinv .* (a @ W1) + b1)        (64 -> 128)
    gemm_kernel<INC1, HIDC, 2, 64, 1><<<(n + 63) / 64, dim3(HIDC, 2)>>>(d_a, W1, b1, d_o1, n);
    // 5) g2 = dinv .* (o1 @ W2)                  (128 -> 64), reuse xs buffer
    gemm_kernel<HIDC, OUTC2, 4, 64, 0><<<(n + 63) / 64, dim3(OUTC2, 4)>>>(d_o1, W2, nullptr, d_xs, n);
    // 6) out[d] = dinv[d] * (g2[d] + sum g2[s]) + b2   (64-ch gather)
    agg64_kernel<1><<<(n * 32 + 255) / 256, 256>>>(d_xs, b2, out, n);
}

// round 4
// speedup vs baseline: 1.5474x; 1.5474x over previous
#include <cuda_runtime.h>
#include <cuda_bf16.h>

// Problem constants (fixed by the dataset)
#define MAXN 100000
#define MAXE 3200000
#define INC1 64
#define HIDC 128
#define OUTC2 64

// ---------------- device scratch (no allocations allowed) ----------------
__device__ float g_buf_o1[MAXN * HIDC];  // relu(layer1 output)            [N,128]
__device__ float g_buf_xs[MAXN * INC1];  // dinv*x, later reused for g2     [N,64]
__device__ float g_buf_a [MAXN * INC1];  // aggregated xs                   [N,64]
__device__ int   g_rowptr[MAXN + 1];
__device__ int   g_cursor[MAXN];
__device__ int   g_col[MAXE];            // CSR col (src ids), grouped by dst
__device__ float g_dinv[MAXN];
__device__ int   g_cnt[MAXN];

// ---------------- CSR build ----------------
__global__ void zero_cnt_kernel(int n) {
    int i = blockIdx.x * blockDim.x + threadIdx.x;
    if (i < n) g_cnt[i] = 0;
}

__global__ void count_kernel(const int* __restrict__ dst, int E) {
    int e = blockIdx.x * blockDim.x + threadIdx.x;
    if (e < E) atomicAdd(&g_cnt[dst[e]], 1);
}

// One-block scan over n counts -> exclusive row_ptr, cursor copy, dinv.
// Degree = cnt + 1 (self loop), always > 0.
__global__ void scan_kernel(int n) {
    __shared__ int sums[1024];
    int t = threadIdx.x;
    int chunk = (n + 1023) >> 10;
    int beg = t * chunk;
    int end = beg + chunk; if (end > n) end = n;
    int s = 0;
    if (beg < n) for (int i = beg; i < end; i++) s += g_cnt[i];
    sums[t] = s;
    __syncthreads();
    for (int off = 1; off < 1024; off <<= 1) {
        int v = sums[t];
        int add = (t >= off) ? sums[t - off] : 0;
        __syncthreads();
        sums[t] = v + add;
        __syncthreads();
    }
    int run = (t == 0) ? 0 : sums[t - 1];
    if (beg < n) {
        for (int i = beg; i < end; i++) {
            g_rowptr[i] = run;
            g_cursor[i] = run;
            g_dinv[i]   = rsqrtf((float)(g_cnt[i] + 1));
            run += g_cnt[i];
        }
    }
    if (t == 1023) g_rowptr[n] = sums[1023];
}

__global__ void fill_kernel(const int* __restrict__ src,
                            const int* __restrict__ dst, int E) {
    int e = blockIdx.x * blockDim.x + threadIdx.x;
    if (e < E) {
        int d = dst[e];
        int pos = atomicAdd(&g_cursor[d], 1);
        g_col[pos] = src[e];
    }
}

// ---------------- xs = dinv .* x (prescale, [N,64]) ----------------
__global__ void scale_x_kernel(const float* __restrict__ X, float* __restrict__ XS, int n) {
    int i = blockIdx.x * blockDim.x + threadIdx.x;      // one float2 per thread
    if (i >= n * 32) return;
    int row = i >> 5;
    float di = g_dinv[row];
    float2 v = ((const float2*)X)[i];
    v.x *= di; v.y *= di;
    ((float2*)XS)[i] = v;
}

// ---------------- Aggregation (CSR gather), one warp per node, 64 ch ----------------
// acc init = G[d] (self-loop term). Optional epilogue: dinv*acc + b (EPI=1), else raw sum.
// Unroll kept at 4: deeper front-batched LDG batches trigger cross-CTA L1tex-queue
// contention (spr_max ~2x at MLP_p1>=12 per B300 measurements).
template <int EPI>
__global__ void __launch_bounds__(256)
agg64_kernel(const float* __restrict__ G, const float* __restrict__ b,
             float* __restrict__ O, int n) {
    int warp = (blockIdx.x * blockDim.x + threadIdx.x) >> 5;
    int lane = threadIdx.x & 31;
    if (warp >= n) return;
    const int d = warp;
    const float2* __restrict__ Gv = (const float2*)G;
    float2 acc = Gv[d * 32 + lane];              // self loop
    int e = g_rowptr[d];
    const int end = g_rowptr[d + 1];
    for (; e + 4 <= end; e += 4) {
        int s0 = g_col[e + 0], s1 = g_col[e + 1], s2 = g_col[e + 2], s3 = g_col[e + 3];
        float2 a0 = Gv[s0 * 32 + lane];
        float2 a1 = Gv[s1 * 32 + lane];
        float2 a2 = Gv[s2 * 32 + lane];
        float2 a3 = Gv[s3 * 32 + lane];
        acc.x += a0.x; acc.y += a0.y;
        acc.x += a1.x; acc.y += a1.y;
        acc.x += a2.x; acc.y += a2.y;
        acc.x += a3.x; acc.y += a3.y;
    }
    for (; e < end; e++) {
        int s = g_col[e];
        float2 a = Gv[s * 32 + lane];
        acc.x += a.x; acc.y += a.y;
    }
    if (EPI) {
        const float di = g_dinv[d];
        float2 bi = ((const float2*)b)[lane];
        acc.x = di * acc.x + bi.x;
        acc.y = di * acc.y + bi.y;
    }
    ((float2*)O)[d * 32 + lane] = acc;
}

// ---------------- GEMM: G[i,:] = epi( X[i,:] @ W ) ----------------
// EPI=1: relu(dinv*acc + b) ; EPI=0: dinv*acc
template <int INC, int OUTC, int RY, int RPB, int EPI>
__global__ void __launch_bounds__(OUTC * RY)
gemm_kernel(const float* __restrict__ X, const float* __restrict__ W,
            const float* __restrict__ b, float* __restrict__ G, int n) {
    __shared__ float Ws[INC * OUTC];
    __shared__ float Xs[RY][INC];
    const int tx = threadIdx.x;        // output channel
    const int ty = threadIdx.y;        // row slot
    const int tid = ty * OUTC + tx;
    const int nthr = OUTC * RY;
    for (int i = tid; i < INC * OUTC; i += nthr) Ws[i] = W[i];
    __syncthreads();
    const int base = blockIdx.x * RPB;
    for (int r0 = 0; r0 < RPB; r0 += RY) {
        for (int i = tid; i < RY * INC; i += nthr) {
            int rr = base + r0 + i / INC;
            Xs[i / INC][i % INC] = (rr < n) ? X[rr * INC + (i % INC)] : 0.f;
        }
        __syncthreads();
        int row = base + r0 + ty;
        if (row < n) {
            float acc = 0.f;
#pragma unroll
            for (int k = 0; k < INC; k++)
                acc += Xs[ty][k] * Ws[k * OUTC + tx];
            float di = g_dinv[row];
            if (EPI) {
                G[row * OUTC + tx] = fmaxf(di * acc + b[tx], 0.f);
            } else {
                G[row * OUTC + tx] = di * acc;
            }
        }
        __syncthreads();
    }
}

// ---------------- launch ----------------
extern "C" void kernel_launch(void* const* d_in, const int* in_sizes, int n_in,
                              void* d_out, int out_size) {
    const float* x  = (const float*)d_in[0];
    const int*   ei = (const int*)d_in[1];     // int32 (JAX x64-disabled truncates int64)
    const float* W1 = (const float*)d_in[2];
    const float* b1 = (const float*)d_in[3];
    const float* W2 = (const float*)d_in[4];
    const float* b2 = (const float*)d_in[5];
    float* out = (float*)d_out;

    const int n = in_sizes[0] / INC1;     // 100000
    const int E = in_sizes[1] / 2;        // 3200000
    const int* src = ei;
    const int* dst = ei + E;

    float* d_o1 = nullptr; cudaGetSymbolAddress((void**)&d_o1, g_buf_o1);
    float* d_xs = nullptr; cudaGetSymbolAddress((void**)&d_xs, g_buf_xs);
    float* d_a  = nullptr; cudaGetSymbolAddress((void**)&d_a,  g_buf_a);

    // 1) CSR build (shared by both layers)
    zero_cnt_kernel<<<(n + 255) / 256, 256>>>(n);
    count_kernel<<<(E + 255) / 256, 256>>>(dst, E);
    scan_kernel<<<1, 1024>>>(n);
    fill_kernel<<<(E + 255) / 256, 256>>>(src, dst, E);

    // 2) xs = dinv .* x   (64 ch)
    scale_x_kernel<<<(n * 32 + 255) / 256, 256>>>(x, d_xs, n);
    // 3) a[d] = xs[d] + sum_{s in N(d)} xs[s]    (64-ch gather)
    agg64_kernel<0><<<(n * 32 + 255) / 256, 256>>>(d_xs, nullptr, d_a, n);
    // 4) o1 = relu(dinv .* (a @ W1) + b1)        (64 -> 128)
    gemm_kernel<INC1, HIDC, 2, 64, 1><<<(n + 63) / 64, dim3(HIDC, 2)>>>(d_a, W1, b1, d_o1, n);
    // 5) g2 = dinv .* (o1 @ W2)                  (128 -> 64), reuse xs buffer
    gemm_kernel<HIDC, OUTC2, 4, 64, 0><<<(n + 63) / 64, dim3(OUTC2, 4)>>>(d_o1, W2, nullptr, d_xs, n);
    // 6) out[d] = dinv[d] * (g2[d] + sum g2[s]) + b2   (64-ch gather)
    agg64_kernel<1><<<(n * 32 + 255) / 256, 256>>>(d_xs, b2, out, n);
}

// round 5
// speedup vs baseline: 3.1039x; 2.0058x over previous
#include <cuda_runtime.h>
#include <cuda_bf16.h>

// Problem constants (fixed by the dataset)
#define MAXN 100000
#define MAXE 3200000
#define INC1 64
#define HIDC 128
#define OUTC2 64
#define SCANB 1024
#define MAXNB 128            // ceil(MAXN/1024) = 98 <= 128

// ---------------- device scratch (no allocations allowed) ----------------
__device__ float g_buf_o1[MAXN * HIDC];  // relu(layer1 output)            [N,128]
__device__ float g_buf_xs[MAXN * INC1];  // dinv*x, later reused for g2     [N,64]
__device__ float g_buf_a [MAXN * INC1];  // aggregated xs                   [N,64]
__device__ int   g_rowptr[MAXN + 1];
__device__ int   g_cursor[MAXN];
__device__ int   g_col[MAXE];            // CSR col (src ids), grouped by dst
__device__ float g_dinv[MAXN];
__device__ int   g_cnt[MAXN];
__device__ int   g_part[MAXNB];
__device__ int   g_partoff[MAXNB];

// ---------------- CSR build ----------------
__global__ void zero_cnt_kernel(int n) {
    int i = blockIdx.x * blockDim.x + threadIdx.x;
    if (i < n) g_cnt[i] = 0;
}

__global__ void count_kernel(const int* __restrict__ dst, int E) {
    int i = blockIdx.x * blockDim.x + threadIdx.x;
    int e = i << 2;
    if (e + 3 < E) {
        int4 d4 = *reinterpret_cast<const int4*>(dst + e);
        atomicAdd(&g_cnt[d4.x], 1);
        atomicAdd(&g_cnt[d4.y], 1);
        atomicAdd(&g_cnt[d4.z], 1);
        atomicAdd(&g_cnt[d4.w], 1);
    } else if (e < E) {
        for (int k = e; k < E; k++) atomicAdd(&g_cnt[dst[k]], 1);
    }
}

// Phase A: per-block sums of g_cnt (grid = nb, block = 1024)
__global__ void blocksum_kernel(int n) {
    __shared__ int wsum[32];
    int i = blockIdx.x * SCANB + threadIdx.x;
    int v = (i < n) ? g_cnt[i] : 0;
    for (int o = 16; o; o >>= 1) v += __shfl_down_sync(0xffffffffu, v, o);
    if ((threadIdx.x & 31) == 0) wsum[threadIdx.x >> 5] = v;
    __syncthreads();
    if (threadIdx.x < 32) {
        int s = wsum[threadIdx.x];
        for (int o = 16; o; o >>= 1) s += __shfl_down_sync(0xffffffffu, s, o);
        if (threadIdx.x == 0) g_part[blockIdx.x] = s;
    }
}

// Phase B: exclusive scan of block sums (1 block, 128 threads, nb <= 128)
__global__ void scanpart_kernel(int nb) {
    __shared__ int sh[MAXNB];
    int t = threadIdx.x;
    int orig = (t < nb) ? g_part[t] : 0;
    sh[t] = orig;
    __syncthreads();
    for (int off = 1; off < MAXNB; off <<= 1) {
        int v = sh[t];
        int add = (t >= off) ? sh[t - off] : 0;
        __syncthreads();
        sh[t] = v + add;
        __syncthreads();
    }
    if (t < nb) g_partoff[t] = sh[t] - orig;   // exclusive prefix
}

// Phase C: per-element exclusive prefix -> rowptr/cursor/dinv (grid = nb, block = 1024)
__global__ void emit_kernel(int n) {
    __shared__ int sh[SCANB];
    int t = threadIdx.x;
    int i = blockIdx.x * SCANB + t;
    int c = (i < n) ? g_cnt[i] : 0;
    sh[t] = c;
    __syncthreads();
    for (int off = 1; off < SCANB; off <<= 1) {
        int v = sh[t];
        int add = (t >= off) ? sh[t - off] : 0;
        __syncthreads();
        sh[t] = v + add;
        __syncthreads();
    }
    int excl = sh[t] - c + g_partoff[blockIdx.x];
    if (i < n) {
        g_rowptr[i] = excl;
        g_cursor[i] = excl;
        g_dinv[i]   = rsqrtf((float)(c + 1));
        if (i == n - 1) g_rowptr[n] = excl + c;
    }
}

__global__ void fill_kernel(const int* __restrict__ src,
                            const int* __restrict__ dst, int E) {
    int i = blockIdx.x * blockDim.x + threadIdx.x;
    int e = i << 2;
    if (e + 3 < E) {
        int4 s4 = *reinterpret_cast<const int4*>(src + e);
        int4 d4 = *reinterpret_cast<const int4*>(dst + e);
        g_col[atomicAdd(&g_cursor[d4.x], 1)] = s4.x;
        g_col[atomicAdd(&g_cursor[d4.y], 1)] = s4.y;
        g_col[atomicAdd(&g_cursor[d4.z], 1)] = s4.z;
        g_col[atomicAdd(&g_cursor[d4.w], 1)] = s4.w;
    } else if (e < E) {
        for (int k = e; k < E; k++)
            g_col[atomicAdd(&g_cursor[dst[k]], 1)] = src[k];
    }
}

// ---------------- xs = dinv .* x (prescale, [N,64]) ----------------
__global__ void scale_x_kernel(const float* __restrict__ X, float* __restrict__ XS, int n) {
    int i = blockIdx.x * blockDim.x + threadIdx.x;      // one float4 per thread
    if (i >= n * 16) return;
    int row = i >> 4;
    float di = g_dinv[row];
    float4 v = ((const float4*)X)[i];
    v.x *= di; v.y *= di; v.z *= di; v.w *= di;
    ((float4*)XS)[i] = v;
}

// ---------------- Aggregation (CSR gather), one warp per node, 64 ch ----------------
// acc init = G[d] (self-loop term). EPI=1: dinv*acc + b, else raw sum.
// Software-pipelined: next batch's 4 indices are loaded before the current batch's
// gathers, breaking the idx->gather dependency chain. Gather batch kept at 4 to
// stay below the cross-CTA L1tex-queue contention knee.
template <int EPI>
__global__ void __launch_bounds__(256)
agg64_kernel(const float* __restrict__ G, const float* __restrict__ b,
             float* __restrict__ O, int n) {
    int warp = (blockIdx.x * blockDim.x + threadIdx.x) >> 5;
    int lane = threadIdx.x & 31;
    if (warp >= n) return;
    const int d = warp;
    const float2* __restrict__ Gv = (const float2*)G;
    float2 acc = Gv[d * 32 + lane];              // self loop
    int e = g_rowptr[d];
    const int end = g_rowptr[d + 1];
    int s0, s1, s2, s3;
    bool have = (e + 4 <= end);
    if (have) { s0 = g_col[e]; s1 = g_col[e+1]; s2 = g_col[e+2]; s3 = g_col[e+3]; }
    while (have) {
        int c0 = s0, c1 = s1, c2 = s2, c3 = s3;
        e += 4;
        have = (e + 4 <= end);
        if (have) { s0 = g_col[e]; s1 = g_col[e+1]; s2 = g_col[e+2]; s3 = g_col[e+3]; }
        float2 a0 = Gv[c0 * 32 + lane];
        float2 a1 = Gv[c1 * 32 + lane];
        float2 a2 = Gv[c2 * 32 + lane];
        float2 a3 = Gv[c3 * 32 + lane];
        acc.x += a0.x; acc.y += a0.y;
        acc.x += a1.x; acc.y += a1.y;
        acc.x += a2.x; acc.y += a2.y;
        acc.x += a3.x; acc.y += a3.y;
    }
    for (; e < end; e++) {
        int s = g_col[e];
        float2 a = Gv[s * 32 + lane];
        acc.x += a.x; acc.y += a.y;
    }
    if (EPI) {
        const float di = g_dinv[d];
        float2 bi = ((const float2*)b)[lane];
        acc.x = di * acc.x + bi.x;
        acc.y = di * acc.y + bi.y;
    }
    ((float2*)O)[d * 32 + lane] = acc;
}

// ---------------- GEMM: G[i,:] = epi( X[i,:] @ W ), RR rows per thread ----------------
// EPI=1: relu(dinv*acc + b) ; EPI=0: dinv*acc
template <int INC, int OUTC, int TY, int RR, int RPB, int EPI>
__global__ void __launch_bounds__(OUTC * TY)
gemm_kernel(const float* __restrict__ X, const float* __restrict__ W,
            const float* __restrict__ b, float* __restrict__ G, int n) {
    __shared__ float Ws[INC * OUTC];
    __shared__ float Xs[TY * RR][INC];
    const int tx = threadIdx.x;        // output channel
    const int ty = threadIdx.y;
    const int tid = ty * OUTC + tx;
    const int nthr = OUTC * TY;
    for (int i = tid; i < INC * OUTC; i += nthr) Ws[i] = W[i];
    __syncthreads();
    const int ROWS = TY * RR;
    const int base = blockIdx.x * RPB;
    for (int r0 = 0; r0 < RPB; r0 += ROWS) {
        // cooperative float4 staging of ROWS rows of X
        for (int i = tid; i < ROWS * (INC / 4); i += nthr) {
            int rloc = i / (INC / 4);
            int cc = (i % (INC / 4));
            int rr = base + r0 + rloc;
            float4 v = (rr < n) ? ((const float4*)(X + rr * INC))[cc]
                                : make_float4(0.f, 0.f, 0.f, 0.f);
            *(float4*)&Xs[rloc][cc * 4] = v;
        }
        __syncthreads();
        float acc[RR];
#pragma unroll
        for (int r = 0; r < RR; r++) acc[r] = 0.f;
#pragma unroll 8
        for (int k = 0; k < INC; k++) {
            float w = Ws[k * OUTC + tx];
#pragma unroll
            for (int r = 0; r < RR; r++)
                acc[r] += Xs[ty * RR + r][k] * w;
        }
#pragma unroll
        for (int r = 0; r < RR; r++) {
            int row = base + r0 + ty * RR + r;
            if (row < n) {
                float di = g_dinv[row];
                float v = EPI ? fmaxf(di * acc[r] + b[tx], 0.f) : di * acc[r];
                G[row * OUTC + tx] = v;
            }
        }
        __syncthreads();
    }
}

// ---------------- launch ----------------
extern "C" void kernel_launch(void* const* d_in, const int* in_sizes, int n_in,
                              void* d_out, int out_size) {
    const float* x  = (const float*)d_in[0];
    const int*   ei = (const int*)d_in[1];     // int32 (JAX x64-disabled truncates int64)
    const float* W1 = (const float*)d_in[2];
    const float* b1 = (const float*)d_in[3];
    const float* W2 = (const float*)d_in[4];
    const float* b2 = (const float*)d_in[5];
    float* out = (float*)d_out;

    const int n = in_sizes[0] / INC1;     // 100000
    const int E = in_sizes[1] / 2;        // 3200000
    const int* src = ei;
    const int* dst = ei + E;
    const int nb = (n + SCANB - 1) / SCANB;   // 98
    const int e4 = (E + 3) / 4;

    float* d_o1 = nullptr; cudaGetSymbolAddress((void**)&d_o1, g_buf_o1);
    float* d_xs = nullptr; cudaGetSymbolAddress((void**)&d_xs, g_buf_xs);
    float* d_a  = nullptr; cudaGetSymbolAddress((void**)&d_a,  g_buf_a);

    // 1) CSR build (shared by both layers)
    zero_cnt_kernel<<<(n + 255) / 256, 256>>>(n);
    count_kernel<<<(e4 + 255) / 256, 256>>>(dst, E);
    blocksum_kernel<<<nb, SCANB>>>(n);
    scanpart_kernel<<<1, MAXNB>>>(nb);
    emit_kernel<<<nb, SCANB>>>(n);
    fill_kernel<<<(e4 + 255) / 256, 256>>>(src, dst, E);

    // 2) xs = dinv .* x   (64 ch)
    scale_x_kernel<<<(n * 16 + 255) / 256, 256>>>(x, d_xs, n);
    // 3) a[d] = xs[d] + sum_{s in N(d)} xs[s]    (64-ch gather)
    agg64_kernel<0><<<(n * 32 + 255) / 256, 256>>>(d_xs, nullptr, d_a, n);
    // 4) o1 = relu(dinv .* (a @ W1) + b1)        (64 -> 128)
    gemm_kernel<INC1, HIDC, 2, 4, 64, 1><<<(n + 63) / 64, dim3(HIDC, 2)>>>(d_a, W1, b1, d_o1, n);
    // 5) g2 = dinv .* (o1 @ W2)                  (128 -> 64), reuse xs buffer
    gemm_kernel<HIDC, OUTC2, 4, 4, 64, 0><<<(n + 63) / 64, dim3(OUTC2, 4)>>>(d_o1, W2, nullptr, d_xs, n);
    // 6) out[d] = dinv[d] * (g2[d] + sum g2[s]) + b2   (64-ch gather)
    agg64_kernel<1><<<(n * 32 + 255) / 256, 256>>>(d_xs, b2, out, n);
}